// round 5
// baseline (speedup 1.0000x reference)
#include <cuda_runtime.h>

#define NN 100000
#define NE 3200000
#define NF 128
#define NH 16
#define MH 100
#define NC 12
#define NG 512
#define NBLK 391   // ceil(NN/256)

// ---- device scratch (static, no allocation; 16B-aligned) ----
__device__ __align__(16) int2  g_csr[NE];         // {src, norm-as-bits}
__device__ __align__(16) int   g_deg[NN];
__device__ __align__(16) int   g_rowstart[NN];
__device__ __align__(16) int   g_cursor[NN];
__device__ __align__(16) int   g_blocksum[512];
__device__ __align__(16) int   g_blockoff[512];
__device__ __align__(16) float g_dinv[NN];
__device__ __align__(16) float g_hpre[NN * NH];   // x @ W1
__device__ __align__(16) float g_hpre2[NN * NH];  // h1 @ W2
__device__ __align__(16) float g_pooled[NG * NH];
__device__ int g_is64;

__device__ __forceinline__ void red4(float* p, float4 v) {
    asm volatile("red.global.add.v4.f32 [%0], {%1,%2,%3,%4};"
                 :: "l"(p), "f"(v.x), "f"(v.y), "f"(v.z), "f"(v.w)
                 : "memory");
}

// ---- dtype probe: int64 buffers viewed as int32 are [v,0,v,0,...] ----
__global__ void k_detect(const int* __restrict__ ei32) {
    int any_nonzero = 0;
    for (int i = 1; i < 128; i += 2) any_nonzero |= ei32[i];
    g_is64 = (any_nonzero == 0) ? 1 : 0;
}

// ---- zero small state ----
__global__ void k_zero() {
    int i = blockIdx.x * blockDim.x + threadIdx.x;
    int stride = gridDim.x * blockDim.x;
    for (int j = i; j < NN; j += stride) g_deg[j] = 0;
    if (i < NG * NH) g_pooled[i] = 0.f;
}

// ---- degree count (reads dst column only) ----
__global__ void k_deg(const void* __restrict__ ei) {
    int e = blockIdx.x * blockDim.x + threadIdx.x;
    if (e >= NE) return;
    int d = g_is64 ? (int)((const long long*)ei)[NE + e]
                   : ((const int*)ei)[NE + e];
    atomicAdd(&g_deg[d], 1);
}

// ---- 3-stage exclusive prefix scan of g_deg -> g_rowstart/g_cursor; dinv fused ----
__global__ void k_scan1() {
    __shared__ int s[256];
    int i = blockIdx.x * 256 + threadIdx.x;
    s[threadIdx.x] = (i < NN) ? g_deg[i] : 0;
    __syncthreads();
    for (int o = 128; o > 0; o >>= 1) {
        if (threadIdx.x < o) s[threadIdx.x] += s[threadIdx.x + o];
        __syncthreads();
    }
    if (threadIdx.x == 0) g_blocksum[blockIdx.x] = s[0];
}
__global__ void k_scan2() {
    __shared__ int s[512];
    int t = threadIdx.x;
    int own = (t < NBLK) ? g_blocksum[t] : 0;
    s[t] = own;
    __syncthreads();
    for (int o = 1; o < 512; o <<= 1) {
        int v = (t >= o) ? s[t - o] : 0;
        __syncthreads();
        s[t] += v;
        __syncthreads();
    }
    if (t < NBLK) g_blockoff[t] = s[t] - own;  // exclusive
}
__global__ void k_scan3() {
    __shared__ int s[256];
    int t = threadIdx.x;
    int i = blockIdx.x * 256 + t;
    int d = (i < NN) ? g_deg[i] : 0;
    s[t] = d;
    __syncthreads();
    for (int o = 1; o < 256; o <<= 1) {
        int v = (t >= o) ? s[t - o] : 0;
        __syncthreads();
        s[t] += v;
        __syncthreads();
    }
    if (i < NN) {
        int start = g_blockoff[blockIdx.x] + s[t] - d;  // exclusive
        g_rowstart[i] = start;
        g_cursor[i]   = start;
        g_dinv[i]     = rsqrtf((float)(d + 1));
    }
}

// ---- CSR fill: csr[slot] = {src, dinv[src]*dinv[dst]} ----
__global__ void k_fill(const void* __restrict__ ei) {
    int e = blockIdx.x * blockDim.x + threadIdx.x;
    if (e >= NE) return;
    int s, d;
    if (g_is64) {
        const long long* p = (const long long*)ei;
        s = (int)p[e];
        d = (int)p[NE + e];
    } else {
        const int* p = (const int*)ei;
        s = p[e];
        d = p[NE + e];
    }
    float nrm = g_dinv[s] * g_dinv[d];
    int slot = atomicAdd(&g_cursor[d], 1);
    g_csr[slot] = make_int2(s, __float_as_int(nrm));
}

// ---- hpre = x @ W1  (100K x 128 x 16) ----
__global__ void k_gemm1(const float* __restrict__ x, const float* __restrict__ W1) {
    __shared__ float w[NF * NH];
    for (int i = threadIdx.x; i < NF * NH; i += blockDim.x) w[i] = W1[i];
    __syncthreads();
    int r = blockIdx.x * blockDim.x + threadIdx.x;
    if (r >= NN) return;
    float acc[NH];
#pragma unroll
    for (int j = 0; j < NH; j++) acc[j] = 0.f;
    const float4* xr = (const float4*)(x + (size_t)r * NF);
    for (int k4 = 0; k4 < NF / 4; k4++) {
        float4 v = __ldg(xr + k4);
        const float* wr = w + k4 * 4 * NH;
#pragma unroll
        for (int j = 0; j < NH; j++)
            acc[j] += v.x * wr[j] + v.y * wr[NH + j] + v.z * wr[2 * NH + j] + v.w * wr[3 * NH + j];
    }
    float4* o = (float4*)(g_hpre + (size_t)r * NH);
#pragma unroll
    for (int j4 = 0; j4 < NH / 4; j4++)
        o[j4] = make_float4(acc[4 * j4], acc[4 * j4 + 1], acc[4 * j4 + 2], acc[4 * j4 + 3]);
}

// ---- helper: accumulate one edge into acc[16] ----
__device__ __forceinline__ void edge_acc(const float* __restrict__ hin, int2 e, float* acc) {
    const float4* row = (const float4*)(hin + (size_t)e.x * NH);
    float w = __int_as_float(e.y);
    float4 v0 = __ldg(row + 0);
    float4 v1 = __ldg(row + 1);
    float4 v2 = __ldg(row + 2);
    float4 v3 = __ldg(row + 3);
    acc[0]  += w * v0.x; acc[1]  += w * v0.y; acc[2]  += w * v0.z; acc[3]  += w * v0.w;
    acc[4]  += w * v1.x; acc[5]  += w * v1.y; acc[6]  += w * v1.z; acc[7]  += w * v1.w;
    acc[8]  += w * v2.x; acc[9]  += w * v2.y; acc[10] += w * v2.z; acc[11] += w * v2.w;
    acc[12] += w * v3.x; acc[13] += w * v3.y; acc[14] += w * v3.z; acc[15] += w * v3.w;
}

// ---- fused: layer-1 aggregation + relu + @W2 -> hpre2 ----
__global__ __launch_bounds__(256) void k_aggfin1(const float* __restrict__ b1,
                                                 const float* __restrict__ W2) {
    __shared__ float w2[NH * NH];
    __shared__ float bs[NH];
    if (threadIdx.x < NH * NH) w2[threadIdx.x] = W2[threadIdx.x];
    if (threadIdx.x < NH) bs[threadIdx.x] = b1[threadIdx.x];
    __syncthreads();
    int dst = blockIdx.x * blockDim.x + threadIdx.x;
    if (dst >= NN) return;
    int start = __ldg(&g_rowstart[dst]);
    int cnt   = __ldg(&g_deg[dst]);
    const int2* p = g_csr + start;
    float acc[NH];
#pragma unroll
    for (int j = 0; j < NH; j++) acc[j] = 0.f;
    int i = 0;
    for (; i + 1 < cnt; i += 2) {
        int2 e0 = __ldg(p + i);
        int2 e1 = __ldg(p + i + 1);
        edge_acc(g_hpre, e0, acc);
        edge_acc(g_hpre, e1, acc);
    }
    if (i < cnt) edge_acc(g_hpre, __ldg(p + i), acc);
    // self loop + bias + relu
    float di = g_dinv[dst];
    float sw = di * di;
    const float4* self = (const float4*)(g_hpre + (size_t)dst * NH);
    float h[NH];
#pragma unroll
    for (int j4 = 0; j4 < 4; j4++) {
        float4 sv = __ldg(self + j4);
        h[4 * j4 + 0] = fmaxf(fmaf(sv.x, sw, acc[4 * j4 + 0]) + bs[4 * j4 + 0], 0.f);
        h[4 * j4 + 1] = fmaxf(fmaf(sv.y, sw, acc[4 * j4 + 1]) + bs[4 * j4 + 1], 0.f);
        h[4 * j4 + 2] = fmaxf(fmaf(sv.z, sw, acc[4 * j4 + 2]) + bs[4 * j4 + 2], 0.f);
        h[4 * j4 + 3] = fmaxf(fmaf(sv.w, sw, acc[4 * j4 + 3]) + bs[4 * j4 + 3], 0.f);
    }
    float o[NH];
#pragma unroll
    for (int j = 0; j < NH; j++) o[j] = 0.f;
#pragma unroll
    for (int j = 0; j < NH; j++) {
        float hj = h[j];
#pragma unroll
        for (int j2 = 0; j2 < NH; j2++) o[j2] += hj * w2[j * NH + j2];
    }
    float4* od = (float4*)(g_hpre2 + (size_t)dst * NH);
#pragma unroll
    for (int j4 = 0; j4 < 4; j4++)
        od[j4] = make_float4(o[4 * j4], o[4 * j4 + 1], o[4 * j4 + 2], o[4 * j4 + 3]);
}

// ---- fused: layer-2 aggregation + relu + global_add_pool ----
__global__ __launch_bounds__(256) void k_aggfin2(const float* __restrict__ b2,
                                                 const void* __restrict__ batch) {
    __shared__ float bs[NH];
    if (threadIdx.x < NH) bs[threadIdx.x] = b2[threadIdx.x];
    __syncthreads();
    int dst = blockIdx.x * blockDim.x + threadIdx.x;
    if (dst >= NN) return;
    int start = __ldg(&g_rowstart[dst]);
    int cnt   = __ldg(&g_deg[dst]);
    const int2* p = g_csr + start;
    float acc[NH];
#pragma unroll
    for (int j = 0; j < NH; j++) acc[j] = 0.f;
    int i = 0;
    for (; i + 1 < cnt; i += 2) {
        int2 e0 = __ldg(p + i);
        int2 e1 = __ldg(p + i + 1);
        edge_acc(g_hpre2, e0, acc);
        edge_acc(g_hpre2, e1, acc);
    }
    if (i < cnt) edge_acc(g_hpre2, __ldg(p + i), acc);
    float di = g_dinv[dst];
    float sw = di * di;
    const float4* self = (const float4*)(g_hpre2 + (size_t)dst * NH);
    int b = g_is64 ? (int)((const long long*)batch)[dst] : ((const int*)batch)[dst];
    float* pool = g_pooled + (size_t)b * NH;
#pragma unroll
    for (int j4 = 0; j4 < 4; j4++) {
        float4 sv = __ldg(self + j4);
        float4 v;
        v.x = fmaxf(fmaf(sv.x, sw, acc[4 * j4 + 0]) + bs[4 * j4 + 0], 0.f);
        v.y = fmaxf(fmaf(sv.y, sw, acc[4 * j4 + 1]) + bs[4 * j4 + 1], 0.f);
        v.z = fmaxf(fmaf(sv.z, sw, acc[4 * j4 + 2]) + bs[4 * j4 + 2], 0.f);
        v.w = fmaxf(fmaf(sv.w, sw, acc[4 * j4 + 3]) + bs[4 * j4 + 3], 0.f);
        red4(pool + 4 * j4, v);
    }
}

// ---- MLP head ----
__global__ void k_head(const float* __restrict__ lw1, const float* __restrict__ lb1,
                       const float* __restrict__ lw2, const float* __restrict__ lb2,
                       float* __restrict__ out) {
    __shared__ float w1s[NH * MH];
    __shared__ float w2s[MH * NC];
    __shared__ float b1s[MH];
    __shared__ float b2s[NC];
    for (int i = threadIdx.x; i < NH * MH; i += blockDim.x) w1s[i] = lw1[i];
    for (int i = threadIdx.x; i < MH * NC; i += blockDim.x) w2s[i] = lw2[i];
    if (threadIdx.x < MH) b1s[threadIdx.x] = lb1[threadIdx.x];
    if (threadIdx.x < NC) b2s[threadIdx.x] = lb2[threadIdx.x];
    __syncthreads();
    int g = blockIdx.x * blockDim.x + threadIdx.x;
    if (g >= NG) return;
    float p[NH];
#pragma unroll
    for (int j = 0; j < NH; j++) p[j] = fmaxf(g_pooled[g * NH + j], 0.f);
    float o[NC];
#pragma unroll
    for (int c = 0; c < NC; c++) o[c] = b2s[c];
    for (int m = 0; m < MH; m++) {
        float hh = b1s[m];
#pragma unroll
        for (int j = 0; j < NH; j++) hh += p[j] * w1s[j * MH + m];
        hh = fmaxf(hh, 0.f);
#pragma unroll
        for (int c = 0; c < NC; c++) o[c] += hh * w2s[m * NC + c];
    }
#pragma unroll
    for (int c = 0; c < NC; c++) out[g * NC + c] = o[c];
}

extern "C" void kernel_launch(void* const* d_in, const int* in_sizes, int n_in,
                              void* d_out, int out_size) {
    const float* x = nullptr;
    const void*  ei = nullptr;
    const void*  batch = nullptr;
    const float *W1 = nullptr, *b1 = nullptr, *W2 = nullptr, *b2 = nullptr;
    const float *lw1 = nullptr, *lb1 = nullptr, *lw2 = nullptr, *lb2 = nullptr;
    for (int i = 0; i < n_in; i++) {
        int sz = in_sizes[i];
        const void* p = d_in[i];
        switch (sz) {
            case NN * NF:   x     = (const float*)p; break;
            case 2 * NE:    ei    = p; break;
            case NN:        batch = p; break;
            case NF * NH:   W1    = (const float*)p; break;
            case NH * NH:   W2    = (const float*)p; break;
            case NH * MH:   lw1   = (const float*)p; break;
            case MH:        lb1   = (const float*)p; break;
            case MH * NC:   lw2   = (const float*)p; break;
            case NC:        lb2   = (const float*)p; break;
            case NH:        if (!b1) b1 = (const float*)p; else b2 = (const float*)p; break;
            default: break;
        }
    }
    float* out = (float*)d_out;

    k_detect<<<1, 1>>>((const int*)ei);
    k_zero<<<512, 256>>>();
    k_deg<<<(NE + 255) / 256, 256>>>(ei);
    k_scan1<<<NBLK, 256>>>();
    k_scan2<<<1, 512>>>();
    k_scan3<<<NBLK, 256>>>();
    k_gemm1<<<NBLK, 256>>>(x, W1);
    k_fill<<<(NE + 255) / 256, 256>>>(ei);
    k_aggfin1<<<NBLK, 256>>>(b1, W2);
    k_aggfin2<<<NBLK, 256>>>(b2, batch);
    k_head<<<(NG + 255) / 256, 256>>>(lw1, lb1, lw2, lb2, out);
}

// round 7
// speedup vs baseline: 1.3682x; 1.3682x over previous
#include <cuda_runtime.h>

#define NN 100000
#define NE 3200000
#define NF 128
#define NH 16
#define MH 100
#define NC 12
#define NG 512
#define NBLK 391        // ceil(NN/256)
#define DEGBLK 12500    // NE/256

// ---- device scratch (static, no allocation; 16B-aligned) ----
__device__ __align__(16) int2  g_csr[NE];         // {src, norm-as-bits}
__device__ __align__(16) int   g_deg[NN];
__device__ __align__(16) int   g_rowstart[NN];
__device__ __align__(16) int   g_cursor[NN];
__device__ __align__(16) int   g_blocksum[512];
__device__ __align__(16) int   g_blockoff[512];
__device__ __align__(16) float g_dinv[NN];
__device__ __align__(16) float g_hpre[NN * NH];   // x @ W1
__device__ __align__(16) float g_hpre2[NN * NH];  // h1 @ W2
__device__ __align__(16) float g_pooled[NG * NH];
__device__ int g_is64;

__device__ __forceinline__ void red4(float* p, float4 v) {
    asm volatile("red.global.add.v4.f32 [%0], {%1,%2,%3,%4};"
                 :: "l"(p), "f"(v.x), "f"(v.y), "f"(v.z), "f"(v.w)
                 : "memory");
}
__device__ __forceinline__ float4 fma4(float s, float4 a, float4 acc) {
    acc.x = fmaf(s, a.x, acc.x); acc.y = fmaf(s, a.y, acc.y);
    acc.z = fmaf(s, a.z, acc.z); acc.w = fmaf(s, a.w, acc.w);
    return acc;
}

// ---- zero small state + dtype probe (int64 viewed as int32 = [v,0,v,0,...]) ----
__global__ void k_zero(const int* __restrict__ ei32) {
    int i = blockIdx.x * blockDim.x + threadIdx.x;
    int stride = gridDim.x * blockDim.x;
    for (int j = i; j < NN; j += stride) g_deg[j] = 0;
    if (i < NG * NH) g_pooled[i] = 0.f;
    if (i == 0) {
        int any_nonzero = 0;
        for (int k = 1; k < 128; k += 2) any_nonzero |= ei32[k];
        g_is64 = (any_nonzero == 0) ? 1 : 0;
    }
}

// ---- fused: gemm1 (blocks [0,NBLK)) + degree count (blocks [NBLK, NBLK+DEGBLK)) ----
__global__ __launch_bounds__(256) void k_prep(const float* __restrict__ x,
                                              const float* __restrict__ W1,
                                              const void* __restrict__ ei) {
    if (blockIdx.x < NBLK) {
        // hpre = x @ W1, float4-vectorized weight access
        __shared__ float4 w4[NF * 4];   // w4[k*4+q] = W1[k][4q..4q+3]
        for (int i = threadIdx.x; i < NF * 4; i += blockDim.x)
            w4[i] = ((const float4*)W1)[i];
        __syncthreads();
        int r = blockIdx.x * blockDim.x + threadIdx.x;
        if (r >= NN) return;
        float4 a0 = make_float4(0.f, 0.f, 0.f, 0.f);
        float4 a1 = a0, a2 = a0, a3 = a0;
        const float4* xr = (const float4*)(x + (size_t)r * NF);
#pragma unroll 4
        for (int k4 = 0; k4 < NF / 4; k4++) {
            float4 xv = __ldg(xr + k4);
            const float4* wr = &w4[(4 * k4) * 4];
            a0 = fma4(xv.x, wr[0], a0); a1 = fma4(xv.x, wr[1], a1);
            a2 = fma4(xv.x, wr[2], a2); a3 = fma4(xv.x, wr[3], a3);
            a0 = fma4(xv.y, wr[4], a0); a1 = fma4(xv.y, wr[5], a1);
            a2 = fma4(xv.y, wr[6], a2); a3 = fma4(xv.y, wr[7], a3);
            a0 = fma4(xv.z, wr[8], a0); a1 = fma4(xv.z, wr[9], a1);
            a2 = fma4(xv.z, wr[10], a2); a3 = fma4(xv.z, wr[11], a3);
            a0 = fma4(xv.w, wr[12], a0); a1 = fma4(xv.w, wr[13], a1);
            a2 = fma4(xv.w, wr[14], a2); a3 = fma4(xv.w, wr[15], a3);
        }
        float4* o = (float4*)(g_hpre + (size_t)r * NH);
        o[0] = a0; o[1] = a1; o[2] = a2; o[3] = a3;
    } else {
        // degree count (reads dst column only)
        int e = (blockIdx.x - NBLK) * blockDim.x + threadIdx.x;
        if (e >= NE) return;
        int d = g_is64 ? (int)((const long long*)ei)[NE + e]
                       : ((const int*)ei)[NE + e];
        atomicAdd(&g_deg[d], 1);
    }
}

// ---- 3-stage exclusive prefix scan of g_deg -> rowstart/cursor; dinv fused ----
__global__ void k_scan1() {
    __shared__ int s[256];
    int i = blockIdx.x * 256 + threadIdx.x;
    s[threadIdx.x] = (i < NN) ? g_deg[i] : 0;
    __syncthreads();
    for (int o = 128; o > 0; o >>= 1) {
        if (threadIdx.x < o) s[threadIdx.x] += s[threadIdx.x + o];
        __syncthreads();
    }
    if (threadIdx.x == 0) g_blocksum[blockIdx.x] = s[0];
}
__global__ void k_scan2() {
    __shared__ int s[512];
    int t = threadIdx.x;
    int own = (t < NBLK) ? g_blocksum[t] : 0;
    s[t] = own;
    __syncthreads();
    for (int o = 1; o < 512; o <<= 1) {
        int v = (t >= o) ? s[t - o] : 0;
        __syncthreads();
        s[t] += v;
        __syncthreads();
    }
    if (t < NBLK) g_blockoff[t] = s[t] - own;
}
__global__ void k_scan3() {
    __shared__ int s[256];
    int t = threadIdx.x;
    int i = blockIdx.x * 256 + t;
    int d = (i < NN) ? g_deg[i] : 0;
    s[t] = d;
    __syncthreads();
    for (int o = 1; o < 256; o <<= 1) {
        int v = (t >= o) ? s[t - o] : 0;
        __syncthreads();
        s[t] += v;
        __syncthreads();
    }
    if (i < NN) {
        int start = g_blockoff[blockIdx.x] + s[t] - d;
        g_rowstart[i] = start;
        g_cursor[i]   = start;
        g_dinv[i]     = rsqrtf((float)(d + 1));
    }
}

// ---- CSR fill: csr[slot] = {src, dinv[src]*dinv[dst]} ----
__global__ void k_fill(const void* __restrict__ ei) {
    int e = blockIdx.x * blockDim.x + threadIdx.x;
    if (e >= NE) return;
    int s, d;
    if (g_is64) {
        const long long* p = (const long long*)ei;
        s = (int)p[e];
        d = (int)p[NE + e];
    } else {
        const int* p = (const int*)ei;
        s = p[e];
        d = p[NE + e];
    }
    float nrm = g_dinv[s] * g_dinv[d];
    int slot = atomicAdd(&g_cursor[d], 1);
    g_csr[slot] = make_int2(s, __float_as_int(nrm));
}

// ---- fused agg+fin, 4 threads per dst (f4 = feature chunk) ----
// LAYER 1: h = relu(agg + self + b1); hpre2 = h @ W2   (shuffle-based)
// LAYER 2: v = relu(agg + self + b2); pool via red4
template <int LAYER>
__global__ __launch_bounds__(256) void k_aggfin(const float* __restrict__ bias,
                                                const float* __restrict__ W2,
                                                const void* __restrict__ batch) {
    __shared__ float4 w2s4[NH * 4];   // [j*4+q] = W2[j][4q..4q+3]
    __shared__ float bs[NH];
    if (LAYER == 1 && threadIdx.x < NH * 4) w2s4[threadIdx.x] = ((const float4*)W2)[threadIdx.x];
    if (threadIdx.x < NH) bs[threadIdx.x] = bias[threadIdx.x];
    __syncthreads();

    int tid = blockIdx.x * blockDim.x + threadIdx.x;
    int dst = tid >> 2;
    int f4  = tid & 3;
    if (dst >= NN) return;
    int start = __ldg(&g_rowstart[dst]);
    int cnt   = __ldg(&g_deg[dst]);
    const float* hin = (LAYER == 1 ? g_hpre : g_hpre2);
    const int2* p = g_csr + start;
    float4 acc = make_float4(0.f, 0.f, 0.f, 0.f);
    int i = 0;
    for (; i + 1 < cnt; i += 2) {
        int2 e0 = __ldg(p + i);
        int2 e1 = __ldg(p + i + 1);
        float4 v0 = __ldg((const float4*)(hin + (size_t)e0.x * NH) + f4);
        float4 v1 = __ldg((const float4*)(hin + (size_t)e1.x * NH) + f4);
        acc = fma4(__int_as_float(e0.y), v0, acc);
        acc = fma4(__int_as_float(e1.y), v1, acc);
    }
    if (i < cnt) {
        int2 e0 = __ldg(p + i);
        float4 v0 = __ldg((const float4*)(hin + (size_t)e0.x * NH) + f4);
        acc = fma4(__int_as_float(e0.y), v0, acc);
    }
    // self loop + bias + relu on own chunk
    float di = g_dinv[dst];
    float sw = di * di;
    float4 sv = __ldg((const float4*)(hin + (size_t)dst * NH) + f4);
    float h[4];
    h[0] = fmaxf(fmaf(sv.x, sw, acc.x) + bs[4 * f4 + 0], 0.f);
    h[1] = fmaxf(fmaf(sv.y, sw, acc.y) + bs[4 * f4 + 1], 0.f);
    h[2] = fmaxf(fmaf(sv.z, sw, acc.z) + bs[4 * f4 + 2], 0.f);
    h[3] = fmaxf(fmaf(sv.w, sw, acc.w) + bs[4 * f4 + 3], 0.f);

    if (LAYER == 1) {
        // o[4*f4..] = sum_j h_full[j] * W2[j][4*f4..]; gather h_full via group shuffles
        int lane = threadIdx.x & 31;
        int base = lane & ~3;
        unsigned gmask = 0xFu << base;
        float4 o = make_float4(0.f, 0.f, 0.f, 0.f);
#pragma unroll
        for (int l = 0; l < 4; l++) {
#pragma unroll
            for (int m = 0; m < 4; m++) {
                float hv = __shfl_sync(gmask, h[m], base + l, 32);
                o = fma4(hv, w2s4[(4 * l + m) * 4 + f4], o);
            }
        }
        ((float4*)(g_hpre2 + (size_t)dst * NH))[f4] = o;
    } else {
        int b = g_is64 ? (int)((const long long*)batch)[dst] : ((const int*)batch)[dst];
        red4(g_pooled + (size_t)b * NH + 4 * f4, make_float4(h[0], h[1], h[2], h[3]));
    }
}

// ---- MLP head ----
__global__ void k_head(const float* __restrict__ lw1, const float* __restrict__ lb1,
                       const float* __restrict__ lw2, const float* __restrict__ lb2,
                       float* __restrict__ out) {
    __shared__ float w1s[NH * MH];
    __shared__ float w2s[MH * NC];
    __shared__ float b1s[MH];
    __shared__ float b2s[NC];
    for (int i = threadIdx.x; i < NH * MH; i += blockDim.x) w1s[i] = lw1[i];
    for (int i = threadIdx.x; i < MH * NC; i += blockDim.x) w2s[i] = lw2[i];
    if (threadIdx.x < MH) b1s[threadIdx.x] = lb1[threadIdx.x];
    if (threadIdx.x < NC) b2s[threadIdx.x] = lb2[threadIdx.x];
    __syncthreads();
    int g = blockIdx.x * blockDim.x + threadIdx.x;
    if (g >= NG) return;
    float p[NH];
#pragma unroll
    for (int j = 0; j < NH; j++) p[j] = fmaxf(g_pooled[g * NH + j], 0.f);
    float o[NC];
#pragma unroll
    for (int c = 0; c < NC; c++) o[c] = b2s[c];
    for (int m = 0; m < MH; m++) {
        float hh = b1s[m];
#pragma unroll
        for (int j = 0; j < NH; j++) hh += p[j] * w1s[j * MH + m];
        hh = fmaxf(hh, 0.f);
#pragma unroll
        for (int c = 0; c < NC; c++) o[c] += hh * w2s[m * NC + c];
    }
#pragma unroll
    for (int c = 0; c < NC; c++) out[g * NC + c] = o[c];
}

extern "C" void kernel_launch(void* const* d_in, const int* in_sizes, int n_in,
                              void* d_out, int out_size) {
    const float* x = nullptr;
    const void*  ei = nullptr;
    const void*  batch = nullptr;
    const float *W1 = nullptr, *b1 = nullptr, *W2 = nullptr, *b2 = nullptr;
    const float *lw1 = nullptr, *lb1 = nullptr, *lw2 = nullptr, *lb2 = nullptr;
    for (int i = 0; i < n_in; i++) {
        int sz = in_sizes[i];
        const void* p = d_in[i];
        switch (sz) {
            case NN * NF:   x     = (const float*)p; break;
            case 2 * NE:    ei    = p; break;
            case NN:        batch = p; break;
            case NF * NH:   W1    = (const float*)p; break;
            case NH * NH:   W2    = (const float*)p; break;
            case NH * MH:   lw1   = (const float*)p; break;
            case MH:        lb1   = (const float*)p; break;
            case MH * NC:   lw2   = (const float*)p; break;
            case NC:        lb2   = (const float*)p; break;
            case NH:        if (!b1) b1 = (const float*)p; else b2 = (const float*)p; break;
            default: break;
        }
    }
    float* out = (float*)d_out;

    k_zero<<<512, 256>>>((const int*)ei);
    k_prep<<<NBLK + DEGBLK, 256>>>(x, W1, ei);
    k_scan1<<<NBLK, 256>>>();
    k_scan2<<<1, 512>>>();
    k_scan3<<<NBLK, 256>>>();
    k_fill<<<(NE + 255) / 256, 256>>>(ei);
    k_aggfin<1><<<(NN * 4 + 255) / 256, 256>>>(b1, W2, nullptr);
    k_aggfin<2><<<(NN * 4 + 255) / 256, 256>>>(b2, nullptr, batch);
    k_head<<<(NG + 255) / 256, 256>>>(lw1, lb1, lw2, lb2, out);
}

// round 8
// speedup vs baseline: 1.3689x; 1.0005x over previous
#include <cuda_runtime.h>

#define NN 100000
#define NE 3200000
#define NF 128
#define NH 16
#define MH 100
#define NC 12
#define NG 512
#define NBLK 391        // ceil(NN/256)
#define DEGBLK 12500    // NE/256

// ---- device scratch (static, no allocation; 16B-aligned).
// g_deg and g_pooled are zero on first use (CUDA zero-init) and re-zeroed by
// their last reader each launch (self-restoring invariant; deterministic).
__device__ __align__(16) int2  g_csr[NE];         // {src, norm-as-bits}
__device__ __align__(16) int   g_deg[NN];
__device__ __align__(16) int   g_rowstart[NN];
__device__ __align__(16) int   g_cursor[NN];
__device__ __align__(16) int   g_blocksum[512];
__device__ __align__(16) float g_dinv[NN];
__device__ __align__(16) float g_hpre[NN * NH];   // x @ W1
__device__ __align__(16) float g_hpre2[NN * NH];  // h1 @ W2
__device__ __align__(16) float g_pooled[NG * NH];

__device__ __forceinline__ void red4(float* p, float4 v) {
    asm volatile("red.global.add.v4.f32 [%0], {%1,%2,%3,%4};"
                 :: "l"(p), "f"(v.x), "f"(v.y), "f"(v.z), "f"(v.w)
                 : "memory");
}
__device__ __forceinline__ float4 fma4(float s, float4 a, float4 acc) {
    acc.x = fmaf(s, a.x, acc.x); acc.y = fmaf(s, a.y, acc.y);
    acc.z = fmaf(s, a.z, acc.z); acc.w = fmaf(s, a.w, acc.w);
    return acc;
}
// int64 buffers viewed as int32 are [v,0,v,0,...]; 8 odd-word samples suffice.
__device__ __forceinline__ int probe64(const int* ei32) {
    int nz = 0;
#pragma unroll
    for (int k = 1; k < 16; k += 2) nz |= ei32[k];
    return nz == 0;
}

// ---- fused: gemm1 (blocks [0,NBLK)) + degree count (blocks [NBLK,NBLK+DEGBLK)) ----
__global__ __launch_bounds__(256) void k_prep(const float* __restrict__ x,
                                              const float* __restrict__ W1,
                                              const void* __restrict__ ei) {
    if (blockIdx.x >= NBLK) {
        __shared__ int is64s;
        if (threadIdx.x == 0) is64s = probe64((const int*)ei);
        __syncthreads();
        int e = (blockIdx.x - NBLK) * blockDim.x + threadIdx.x;
        if (e >= NE) return;
        int d = is64s ? (int)((const long long*)ei)[NE + e]
                      : ((const int*)ei)[NE + e];
        atomicAdd(&g_deg[d], 1);
        return;
    }
    // hpre = x @ W1, float4-vectorized weight access
    __shared__ float4 w4[NF * 4];   // w4[k*4+q] = W1[k][4q..4q+3]
    for (int i = threadIdx.x; i < NF * 4; i += blockDim.x)
        w4[i] = ((const float4*)W1)[i];
    __syncthreads();
    int r = blockIdx.x * blockDim.x + threadIdx.x;
    if (r >= NN) return;
    float4 a0 = make_float4(0.f, 0.f, 0.f, 0.f);
    float4 a1 = a0, a2 = a0, a3 = a0;
    const float4* xr = (const float4*)(x + (size_t)r * NF);
#pragma unroll 4
    for (int k4 = 0; k4 < NF / 4; k4++) {
        float4 xv = __ldg(xr + k4);
        const float4* wr = &w4[(4 * k4) * 4];
        a0 = fma4(xv.x, wr[0], a0); a1 = fma4(xv.x, wr[1], a1);
        a2 = fma4(xv.x, wr[2], a2); a3 = fma4(xv.x, wr[3], a3);
        a0 = fma4(xv.y, wr[4], a0); a1 = fma4(xv.y, wr[5], a1);
        a2 = fma4(xv.y, wr[6], a2); a3 = fma4(xv.y, wr[7], a3);
        a0 = fma4(xv.z, wr[8], a0); a1 = fma4(xv.z, wr[9], a1);
        a2 = fma4(xv.z, wr[10], a2); a3 = fma4(xv.z, wr[11], a3);
        a0 = fma4(xv.w, wr[12], a0); a1 = fma4(xv.w, wr[13], a1);
        a2 = fma4(xv.w, wr[14], a2); a3 = fma4(xv.w, wr[15], a3);
    }
    float4* o = (float4*)(g_hpre + (size_t)r * NH);
    o[0] = a0; o[1] = a1; o[2] = a2; o[3] = a3;
}

// ---- scanA: per-block sums of g_deg ----
__global__ void k_scanA() {
    __shared__ int s[256];
    int i = blockIdx.x * 256 + threadIdx.x;
    s[threadIdx.x] = (i < NN) ? g_deg[i] : 0;
    __syncthreads();
    for (int o = 128; o > 0; o >>= 1) {
        if (threadIdx.x < o) s[threadIdx.x] += s[threadIdx.x + o];
        __syncthreads();
    }
    if (threadIdx.x == 0) g_blocksum[blockIdx.x] = s[0];
}

// ---- scanB: block-offset reduction + local scan -> rowstart/cursor/dinv ----
__global__ void k_scanB() {
    __shared__ int s[256];
    __shared__ int off;
    int t = threadIdx.x;
    int b = blockIdx.x;
    // exclusive prefix of blocksum[0..b-1] via reduction
    int v = 0;
    if (t < b) v = g_blocksum[t];
    if (t + 256 < b) v += g_blocksum[t + 256];
    s[t] = v;
    __syncthreads();
    for (int o = 128; o > 0; o >>= 1) {
        if (t < o) s[t] += s[t + o];
        __syncthreads();
    }
    if (t == 0) off = s[0];
    __syncthreads();
    // local inclusive scan of deg
    int i = b * 256 + t;
    int d = (i < NN) ? g_deg[i] : 0;
    s[t] = d;
    __syncthreads();
    for (int o = 1; o < 256; o <<= 1) {
        int vv = (t >= o) ? s[t - o] : 0;
        __syncthreads();
        s[t] += vv;
        __syncthreads();
    }
    if (i < NN) {
        int start = off + s[t] - d;
        g_rowstart[i] = start;
        g_cursor[i]   = start;
        g_dinv[i]     = rsqrtf((float)(d + 1));
    }
}

// ---- CSR fill: csr[slot] = {src, dinv[src]*dinv[dst]} ----
__global__ void k_fill(const void* __restrict__ ei) {
    __shared__ int is64s;
    if (threadIdx.x == 0) is64s = probe64((const int*)ei);
    __syncthreads();
    int e = blockIdx.x * blockDim.x + threadIdx.x;
    if (e >= NE) return;
    int s, d;
    if (is64s) {
        const long long* p = (const long long*)ei;
        s = (int)p[e];
        d = (int)p[NE + e];
    } else {
        const int* p = (const int*)ei;
        s = p[e];
        d = p[NE + e];
    }
    float nrm = g_dinv[s] * g_dinv[d];
    int slot = atomicAdd(&g_cursor[d], 1);
    g_csr[slot] = make_int2(s, __float_as_int(nrm));
}

// ---- fused agg+fin, 4 threads per dst (f4 = feature chunk), 4-way unrolled ----
// LAYER 1: h = relu(agg + self + b1); hpre2 = h @ W2   (shuffle-based)
// LAYER 2: v = relu(agg + self + b2); pool via red4; re-zero g_deg
template <int LAYER>
__global__ __launch_bounds__(256) void k_aggfin(const float* __restrict__ bias,
                                                const float* __restrict__ W2,
                                                const void* __restrict__ batch,
                                                const void* __restrict__ ei) {
    __shared__ float4 w2s4[NH * 4];   // [j*4+q] = W2[j][4q..4q+3]
    __shared__ float bs[NH];
    __shared__ int is64s;
    if (LAYER == 1 && threadIdx.x < NH * 4) w2s4[threadIdx.x] = ((const float4*)W2)[threadIdx.x];
    if (threadIdx.x < NH) bs[threadIdx.x] = bias[threadIdx.x];
    if (LAYER == 2 && threadIdx.x == 0) is64s = probe64((const int*)ei);
    __syncthreads();

    int tid = blockIdx.x * blockDim.x + threadIdx.x;
    int dst = tid >> 2;
    int f4  = tid & 3;
    if (dst >= NN) return;
    int start = __ldg(&g_rowstart[dst]);
    int cnt   = __ldg(&g_deg[dst]);
    if (LAYER == 2 && f4 == 0) g_deg[dst] = 0;   // self-restore for next launch
    const float* hin = (LAYER == 1 ? g_hpre : g_hpre2);
    const int2* p = g_csr + start;
    float4 acc = make_float4(0.f, 0.f, 0.f, 0.f);
    float4 acc2 = acc;
    int i = 0;
    for (; i + 3 < cnt; i += 4) {
        int2 e0 = __ldg(p + i);
        int2 e1 = __ldg(p + i + 1);
        int2 e2 = __ldg(p + i + 2);
        int2 e3 = __ldg(p + i + 3);
        float4 v0 = __ldg((const float4*)(hin + (size_t)e0.x * NH) + f4);
        float4 v1 = __ldg((const float4*)(hin + (size_t)e1.x * NH) + f4);
        float4 v2 = __ldg((const float4*)(hin + (size_t)e2.x * NH) + f4);
        float4 v3 = __ldg((const float4*)(hin + (size_t)e3.x * NH) + f4);
        acc  = fma4(__int_as_float(e0.y), v0, acc);
        acc2 = fma4(__int_as_float(e1.y), v1, acc2);
        acc  = fma4(__int_as_float(e2.y), v2, acc);
        acc2 = fma4(__int_as_float(e3.y), v3, acc2);
    }
    for (; i < cnt; i++) {
        int2 e0 = __ldg(p + i);
        float4 v0 = __ldg((const float4*)(hin + (size_t)e0.x * NH) + f4);
        acc = fma4(__int_as_float(e0.y), v0, acc);
    }
    acc.x += acc2.x; acc.y += acc2.y; acc.z += acc2.z; acc.w += acc2.w;
    // self loop + bias + relu on own chunk
    float di = g_dinv[dst];
    float sw = di * di;
    float4 sv = __ldg((const float4*)(hin + (size_t)dst * NH) + f4);
    float h[4];
    h[0] = fmaxf(fmaf(sv.x, sw, acc.x) + bs[4 * f4 + 0], 0.f);
    h[1] = fmaxf(fmaf(sv.y, sw, acc.y) + bs[4 * f4 + 1], 0.f);
    h[2] = fmaxf(fmaf(sv.z, sw, acc.z) + bs[4 * f4 + 2], 0.f);
    h[3] = fmaxf(fmaf(sv.w, sw, acc.w) + bs[4 * f4 + 3], 0.f);

    if (LAYER == 1) {
        // o[4*f4..] = sum_j h_full[j] * W2[j][4*f4..]; gather h_full via group shuffles
        int lane = threadIdx.x & 31;
        int base = lane & ~3;
        unsigned gmask = 0xFu << base;
        float4 o = make_float4(0.f, 0.f, 0.f, 0.f);
#pragma unroll
        for (int l = 0; l < 4; l++) {
#pragma unroll
            for (int m = 0; m < 4; m++) {
                float hv = __shfl_sync(gmask, h[m], base + l, 32);
                o = fma4(hv, w2s4[(4 * l + m) * 4 + f4], o);
            }
        }
        ((float4*)(g_hpre2 + (size_t)dst * NH))[f4] = o;
    } else {
        int b = is64s ? (int)((const long long*)batch)[dst] : ((const int*)batch)[dst];
        red4(g_pooled + (size_t)b * NH + 4 * f4, make_float4(h[0], h[1], h[2], h[3]));
    }
}

// ---- MLP head (re-zeroes g_pooled after reading) ----
__global__ void k_head(const float* __restrict__ lw1, const float* __restrict__ lb1,
                       const float* __restrict__ lw2, const float* __restrict__ lb2,
                       float* __restrict__ out) {
    __shared__ float w1s[NH * MH];
    __shared__ float w2s[MH * NC];
    __shared__ float b1s[MH];
    __shared__ float b2s[NC];
    for (int i = threadIdx.x; i < NH * MH; i += blockDim.x) w1s[i] = lw1[i];
    for (int i = threadIdx.x; i < MH * NC; i += blockDim.x) w2s[i] = lw2[i];
    if (threadIdx.x < MH) b1s[threadIdx.x] = lb1[threadIdx.x];
    if (threadIdx.x < NC) b2s[threadIdx.x] = lb2[threadIdx.x];
    __syncthreads();
    int g = blockIdx.x * blockDim.x + threadIdx.x;
    if (g >= NG) return;
    float p[NH];
#pragma unroll
    for (int j = 0; j < NH; j++) {
        p[j] = fmaxf(g_pooled[g * NH + j], 0.f);
        g_pooled[g * NH + j] = 0.f;   // self-restore for next launch
    }
    float o[NC];
#pragma unroll
    for (int c = 0; c < NC; c++) o[c] = b2s[c];
    for (int m = 0; m < MH; m++) {
        float hh = b1s[m];
#pragma unroll
        for (int j = 0; j < NH; j++) hh += p[j] * w1s[j * MH + m];
        hh = fmaxf(hh, 0.f);
#pragma unroll
        for (int c = 0; c < NC; c++) o[c] += hh * w2s[m * NC + c];
    }
#pragma unroll
    for (int c = 0; c < NC; c++) out[g * NC + c] = o[c];
}

extern "C" void kernel_launch(void* const* d_in, const int* in_sizes, int n_in,
                              void* d_out, int out_size) {
    const float* x = nullptr;
    const void*  ei = nullptr;
    const void*  batch = nullptr;
    const float *W1 = nullptr, *b1 = nullptr, *W2 = nullptr, *b2 = nullptr;
    const float *lw1 = nullptr, *lb1 = nullptr, *lw2 = nullptr, *lb2 = nullptr;
    for (int i = 0; i < n_in; i++) {
        int sz = in_sizes[i];
        const void* p = d_in[i];
        switch (sz) {
            case NN * NF:   x     = (const float*)p; break;
            case 2 * NE:    ei    = p; break;
            case NN:        batch = p; break;
            case NF * NH:   W1    = (const float*)p; break;
            case NH * NH:   W2    = (const float*)p; break;
            case NH * MH:   lw1   = (const float*)p; break;
            case MH:        lb1   = (const float*)p; break;
            case MH * NC:   lw2   = (const float*)p; break;
            case NC:        lb2   = (const float*)p; break;
            case NH:        if (!b1) b1 = (const float*)p; else b2 = (const float*)p; break;
            default: break;
        }
    }
    float* out = (float*)d_out;

    k_prep<<<NBLK + DEGBLK, 256>>>(x, W1, ei);
    k_scanA<<<NBLK, 256>>>();
    k_scanB<<<NBLK, 256>>>();
    k_fill<<<(NE + 255) / 256, 256>>>(ei);
    k_aggfin<1><<<(NN * 4 + 255) / 256, 256>>>(b1, W2, nullptr, nullptr);
    k_aggfin<2><<<(NN * 4 + 255) / 256, 256>>>(b2, nullptr, batch, ei);
    k_head<<<(NG + 255) / 256, 256>>>(lw1, lb1, lw2, lb2, out);
}

// round 10
// speedup vs baseline: 1.4948x; 1.0920x over previous
#include <cuda_runtime.h>

#define NN 100000
#define NE 3200000
#define NF 128
#define NH 16
#define MH 100
#define NC 12
#define NG 512
#define NBLK 391        // ceil(NN/256)
#define FILLBLK 12500   // NE/256
#define CSRCAP (NE + 3 * NN)   // rowstarts padded to multiples of 4

// ---- device scratch (static, no allocation; 16B-aligned).
// g_deg / g_pooled: zero-init by CUDA, re-zeroed by last reader per launch.
__device__ __align__(16) int   g_csr[CSRCAP];     // src index only
__device__ __align__(16) int   g_deg[NN];
__device__ __align__(16) int   g_rowstart[NN];
__device__ __align__(16) int   g_cursor[NN];
__device__ __align__(16) int   g_blocksum[512];
__device__ __align__(16) float g_dinv[NN];
__device__ __align__(16) float g_hpre[NN * NH];   // dinv * (x @ W1)
__device__ __align__(16) float g_hpre2[NN * NH];  // dinv * (h1 @ W2)
__device__ __align__(16) float g_pooled[NG * NH];

__device__ __forceinline__ void red4(float* p, float4 v) {
    asm volatile("red.global.add.v4.f32 [%0], {%1,%2,%3,%4};"
                 :: "l"(p), "f"(v.x), "f"(v.y), "f"(v.z), "f"(v.w)
                 : "memory");
}
__device__ __forceinline__ float4 fma4(float s, float4 a, float4 acc) {
    acc.x = fmaf(s, a.x, acc.x); acc.y = fmaf(s, a.y, acc.y);
    acc.z = fmaf(s, a.z, acc.z); acc.w = fmaf(s, a.w, acc.w);
    return acc;
}
__device__ __forceinline__ float4 add4(float4 a, float4 b) {
    a.x += b.x; a.y += b.y; a.z += b.z; a.w += b.w; return a;
}
// int64 buffers viewed as int32 are [v,0,v,0,...]; sample odd words of the
// EDGE INDEX ONLY (batch_vec is sorted -> leading zeros are legitimate there).
__device__ __forceinline__ int probe64(const int* p32) {
    int nz = 0;
#pragma unroll
    for (int k = 1; k < 16; k += 2) nz |= p32[k];
    return nz == 0;
}

// ---- degree count (reads dst column only) ----
__global__ __launch_bounds__(256) void k_deg(const void* __restrict__ ei) {
    __shared__ int is64s;
    if (threadIdx.x == 0) is64s = probe64((const int*)ei);
    __syncthreads();
    int e = blockIdx.x * blockDim.x + threadIdx.x;
    if (e >= NE) return;
    int d = is64s ? (int)((const long long*)ei)[NE + e]
                  : ((const int*)ei)[NE + e];
    atomicAdd(&g_deg[d], 1);
}

// ---- scanA: per-block sums of padded degrees ----
__global__ void k_scanA() {
    __shared__ int s[256];
    int i = blockIdx.x * 256 + threadIdx.x;
    s[threadIdx.x] = (i < NN) ? ((g_deg[i] + 3) & ~3) : 0;
    __syncthreads();
    for (int o = 128; o > 0; o >>= 1) {
        if (threadIdx.x < o) s[threadIdx.x] += s[threadIdx.x + o];
        __syncthreads();
    }
    if (threadIdx.x == 0) g_blocksum[blockIdx.x] = s[0];
}

// ---- scanB: block-offset reduction + local scan -> rowstart/cursor/dinv ----
__global__ void k_scanB() {
    __shared__ int s[256];
    __shared__ int off;
    int t = threadIdx.x;
    int b = blockIdx.x;
    int v = 0;
    if (t < b) v = g_blocksum[t];
    if (t + 256 < b) v += g_blocksum[t + 256];
    s[t] = v;
    __syncthreads();
    for (int o = 128; o > 0; o >>= 1) {
        if (t < o) s[t] += s[t + o];
        __syncthreads();
    }
    if (t == 0) off = s[0];
    __syncthreads();
    int i = b * 256 + t;
    int d  = (i < NN) ? g_deg[i] : 0;
    int d4 = (d + 3) & ~3;
    s[t] = d4;
    __syncthreads();
    for (int o = 1; o < 256; o <<= 1) {
        int vv = (t >= o) ? s[t - o] : 0;
        __syncthreads();
        s[t] += vv;
        __syncthreads();
    }
    if (i < NN) {
        int start = off + s[t] - d4;
        g_rowstart[i] = start;
        g_cursor[i]   = start;
        g_dinv[i]     = rsqrtf((float)(d + 1));
    }
}

// ---- fused fill + gemm1, interleaved (every 33rd block is a gemm block) ----
// fill:  csr[slot] = src (4B)
// gemm:  hpre[r] = dinv[r] * (x[r] @ W1)
__global__ __launch_bounds__(256) void k_fillgemm(const float* __restrict__ x,
                                                  const float* __restrict__ W1,
                                                  const void* __restrict__ ei) {
    int g = blockIdx.x;
    bool is_gemm = (g % 33 == 0) && (g / 33 < NBLK);
    if (!is_gemm) {
        __shared__ int is64s;
        if (threadIdx.x == 0) is64s = probe64((const int*)ei);
        __syncthreads();
        int fb = g - g / 33 - 1;           // fill block index 0..FILLBLK-1
        int e = fb * 256 + threadIdx.x;
        if (e >= NE) return;
        int s, d;
        if (is64s) {
            const long long* p = (const long long*)ei;
            s = (int)p[e];
            d = (int)p[NE + e];
        } else {
            const int* p = (const int*)ei;
            s = p[e];
            d = p[NE + e];
        }
        int slot = atomicAdd(&g_cursor[d], 1);
        g_csr[slot] = s;
        return;
    }
    // gemm part
    __shared__ float4 w4[NF * 4];   // w4[k*4+q] = W1[k][4q..4q+3]
    for (int i = threadIdx.x; i < NF * 4; i += blockDim.x)
        w4[i] = ((const float4*)W1)[i];
    __syncthreads();
    int r = (g / 33) * 256 + threadIdx.x;
    if (r >= NN) return;
    float4 a0 = make_float4(0.f, 0.f, 0.f, 0.f);
    float4 a1 = a0, a2 = a0, a3 = a0;
    const float4* xr = (const float4*)(x + (size_t)r * NF);
#pragma unroll 4
    for (int k4 = 0; k4 < NF / 4; k4++) {
        float4 xv = __ldg(xr + k4);
        const float4* wr = &w4[(4 * k4) * 4];
        a0 = fma4(xv.x, wr[0], a0); a1 = fma4(xv.x, wr[1], a1);
        a2 = fma4(xv.x, wr[2], a2); a3 = fma4(xv.x, wr[3], a3);
        a0 = fma4(xv.y, wr[4], a0); a1 = fma4(xv.y, wr[5], a1);
        a2 = fma4(xv.y, wr[6], a2); a3 = fma4(xv.y, wr[7], a3);
        a0 = fma4(xv.z, wr[8], a0); a1 = fma4(xv.z, wr[9], a1);
        a2 = fma4(xv.z, wr[10], a2); a3 = fma4(xv.z, wr[11], a3);
        a0 = fma4(xv.w, wr[12], a0); a1 = fma4(xv.w, wr[13], a1);
        a2 = fma4(xv.w, wr[14], a2); a3 = fma4(xv.w, wr[15], a3);
    }
    float di = g_dinv[r];
    float4 z = make_float4(0.f, 0.f, 0.f, 0.f);
    float4* o = (float4*)(g_hpre + (size_t)r * NH);
    o[0] = fma4(di, a0, z);
    o[1] = fma4(di, a1, z);
    o[2] = fma4(di, a2, z);
    o[3] = fma4(di, a3, z);
}

// ---- fused agg+fin, 4 threads per dst (f4 = feature chunk), int4 index reads ----
// out_pre[d] = dinv[d] * (sum_{s in N(d)} hs[s] + hs[d])
// LAYER 1: h = relu(out_pre + b1); hpre2 = dinv[d] * (h @ W2)  (shuffle-based)
// LAYER 2: v = relu(out_pre + b2); pool via red4; re-zero g_deg
template <int LAYER>
__global__ __launch_bounds__(256) void k_aggfin(const float* __restrict__ bias,
                                                const float* __restrict__ W2,
                                                const void* __restrict__ batch,
                                                const void* __restrict__ ei) {
    __shared__ float4 w2s4[NH * 4];   // [j*4+q] = W2[j][4q..4q+3]
    __shared__ float bs[NH];
    __shared__ int is64s;
    if (LAYER == 1 && threadIdx.x < NH * 4) w2s4[threadIdx.x] = ((const float4*)W2)[threadIdx.x];
    if (threadIdx.x < NH) bs[threadIdx.x] = bias[threadIdx.x];
    if (LAYER == 2 && threadIdx.x == 0) is64s = probe64((const int*)ei);  // probe EI, not batch!
    __syncthreads();

    int tid = blockIdx.x * blockDim.x + threadIdx.x;
    int dst = tid >> 2;
    int f4  = tid & 3;
    if (dst >= NN) return;
    int start = __ldg(&g_rowstart[dst]);
    int cnt   = __ldg(&g_deg[dst]);
    if (LAYER == 2 && f4 == 0) g_deg[dst] = 0;   // self-restore for next launch
    const float* hin = (LAYER == 1 ? g_hpre : g_hpre2);
    const int4* p4 = (const int4*)(g_csr + start);   // start is 4-aligned
    float4 acc = make_float4(0.f, 0.f, 0.f, 0.f);
    float4 acc2 = acc;
    int n4 = cnt >> 2;
    for (int k = 0; k < n4; k++) {
        int4 e = __ldg(p4 + k);
        float4 v0 = __ldg((const float4*)(hin + (size_t)e.x * NH) + f4);
        float4 v1 = __ldg((const float4*)(hin + (size_t)e.y * NH) + f4);
        float4 v2 = __ldg((const float4*)(hin + (size_t)e.z * NH) + f4);
        float4 v3 = __ldg((const float4*)(hin + (size_t)e.w * NH) + f4);
        acc  = add4(acc,  add4(v0, v1));
        acc2 = add4(acc2, add4(v2, v3));
    }
    const int* ps = g_csr + start;
    for (int i = n4 << 2; i < cnt; i++) {
        int s = __ldg(ps + i);
        acc = add4(acc, __ldg((const float4*)(hin + (size_t)s * NH) + f4));
    }
    acc = add4(acc, acc2);
    // self loop, then scale by dinv[dst], bias, relu
    acc = add4(acc, __ldg((const float4*)(hin + (size_t)dst * NH) + f4));
    float di = g_dinv[dst];
    float h[4];
    h[0] = fmaxf(fmaf(di, acc.x, bs[4 * f4 + 0]), 0.f);
    h[1] = fmaxf(fmaf(di, acc.y, bs[4 * f4 + 1]), 0.f);
    h[2] = fmaxf(fmaf(di, acc.z, bs[4 * f4 + 2]), 0.f);
    h[3] = fmaxf(fmaf(di, acc.w, bs[4 * f4 + 3]), 0.f);

    if (LAYER == 1) {
        // o[4*f4..] = sum_j h_full[j] * W2[j][4*f4..]; gather h_full via group shuffles
        int lane = threadIdx.x & 31;
        int base = lane & ~3;
        unsigned gmask = 0xFu << base;
        float4 o = make_float4(0.f, 0.f, 0.f, 0.f);
#pragma unroll
        for (int l = 0; l < 4; l++) {
#pragma unroll
            for (int m = 0; m < 4; m++) {
                float hv = __shfl_sync(gmask, h[m], base + l, 32);
                o = fma4(hv, w2s4[(4 * l + m) * 4 + f4], o);
            }
        }
        // pre-scale for layer 2: hpre2 = dinv[d] * (h1 @ W2)
        o.x *= di; o.y *= di; o.z *= di; o.w *= di;
        ((float4*)(g_hpre2 + (size_t)dst * NH))[f4] = o;
    } else {
        int b = is64s ? (int)((const long long*)batch)[dst] : ((const int*)batch)[dst];
        red4(g_pooled + (size_t)b * NH + 4 * f4, make_float4(h[0], h[1], h[2], h[3]));
    }
}

// ---- MLP head (re-zeroes g_pooled after reading) ----
__global__ void k_head(const float* __restrict__ lw1, const float* __restrict__ lb1,
                       const float* __restrict__ lw2, const float* __restrict__ lb2,
                       float* __restrict__ out) {
    __shared__ float w1s[NH * MH];
    __shared__ float w2s[MH * NC];
    __shared__ float b1s[MH];
    __shared__ float b2s[NC];
    for (int i = threadIdx.x; i < NH * MH; i += blockDim.x) w1s[i] = lw1[i];
    for (int i = threadIdx.x; i < MH * NC; i += blockDim.x) w2s[i] = lw2[i];
    if (threadIdx.x < MH) b1s[threadIdx.x] = lb1[threadIdx.x];
    if (threadIdx.x < NC) b2s[threadIdx.x] = lb2[threadIdx.x];
    __syncthreads();
    int g = blockIdx.x * blockDim.x + threadIdx.x;
    if (g >= NG) return;
    float p[NH];
#pragma unroll
    for (int j = 0; j < NH; j++) {
        p[j] = fmaxf(g_pooled[g * NH + j], 0.f);
        g_pooled[g * NH + j] = 0.f;   // self-restore for next launch
    }
    float o[NC];
#pragma unroll
    for (int c = 0; c < NC; c++) o[c] = b2s[c];
    for (int m = 0; m < MH; m++) {
        float hh = b1s[m];
#pragma unroll
        for (int j = 0; j < NH; j++) hh += p[j] * w1s[j * MH + m];
        hh = fmaxf(hh, 0.f);
#pragma unroll
        for (int c = 0; c < NC; c++) o[c] += hh * w2s[m * NC + c];
    }
#pragma unroll
    for (int c = 0; c < NC; c++) out[g * NC + c] = o[c];
}

extern "C" void kernel_launch(void* const* d_in, const int* in_sizes, int n_in,
                              void* d_out, int out_size) {
    const float* x = nullptr;
    const void*  ei = nullptr;
    const void*  batch = nullptr;
    const float *W1 = nullptr, *b1 = nullptr, *W2 = nullptr, *b2 = nullptr;
    const float *lw1 = nullptr, *lb1 = nullptr, *lw2 = nullptr, *lb2 = nullptr;
    for (int i = 0; i < n_in; i++) {
        int sz = in_sizes[i];
        const void* p = d_in[i];
        switch (sz) {
            case NN * NF:   x     = (const float*)p; break;
            case 2 * NE:    ei    = p; break;
            case NN:        batch = p; break;
            case NF * NH:   W1    = (const float*)p; break;
            case NH * NH:   W2    = (const float*)p; break;
            case NH * MH:   lw1   = (const float*)p; break;
            case MH:        lb1   = (const float*)p; break;
            case MH * NC:   lw2   = (const float*)p; break;
            case NC:        lb2   = (const float*)p; break;
            case NH:        if (!b1) b1 = (const float*)p; else b2 = (const float*)p; break;
            default: break;
        }
    }
    float* out = (float*)d_out;

    k_deg<<<FILLBLK, 256>>>(ei);
    k_scanA<<<NBLK, 256>>>();
    k_scanB<<<NBLK, 256>>>();
    k_fillgemm<<<FILLBLK + NBLK, 256>>>(x, W1, ei);
    k_aggfin<1><<<(NN * 4 + 255) / 256, 256>>>(b1, W2, nullptr, nullptr);
    k_aggfin<2><<<(NN * 4 + 255) / 256, 256>>>(b2, nullptr, batch, ei);
    k_head<<<(NG + 255) / 256, 256>>>(lw1, lb1, lw2, lb2, out);
}